// round 12
// baseline (speedup 1.0000x reference)
#include <cuda_runtime.h>

// Shapes fixed by the problem: B=4, T=2048, D=768 -> E=2*D=1536, H=256.
#define B_DIM 4
#define T_DIM 2048
#define E_DIM 1536
#define H_DIM 256

#define NTHREADS  384                      // one thread per float4 column
#define COLS4     (E_DIM / 4)              // 384
#define CHUNKS_PB 74                       // chunks per batch element
#define N_BLOCKS  (B_DIM * CHUNKS_PB)      // 296 = 148 SMs x 2 exactly
#define BIG_CH    50                       // 50 chunks of 28 rows + 24 of 27
#define N_TAIL    32
#define D_CHUNK   (E_DIM / N_TAIL)         // 48

// Scratch: __device__ globals (allocation-free rule).
// g_part / g_hpart are FULLY overwritten every call (plain stores) -> no
// reset needed. Only the two counters are reset by the last-arriving block.
__device__ float             g_part[CHUNKS_PB][B_DIM * E_DIM];  // 1.8 MB
__device__ float             g_hpart[N_TAIL][B_DIM][H_DIM];
__device__ volatile unsigned g_c1;
__device__ unsigned          g_c2;

__global__ void __launch_bounds__(NTHREADS, 2)
curiosity_fused(const float* __restrict__ x,
                const float* __restrict__ W1,
                const float* __restrict__ b1,
                const float* __restrict__ W2,
                const float* __restrict__ b2,
                float* __restrict__ out, int out_size) {
    const int tid = threadIdx.x;
    const int bid = blockIdx.x;

    // ---------------- Phase 1: balanced column sum (all 296 blocks) --------
    // Block = (batch b, chunk c). Chunks partition T=2048 into 74 pieces of
    // 28/27 rows -> every SM carries exactly 2 blocks, ~355 KB. Thread owns
    // float4 column tid (384 threads = full row). Fully coalesced.
    {
        const int b     = bid / CHUNKS_PB;
        const int c     = bid % CHUNKS_PB;
        const int t0    = (c < BIG_CH) ? c * 28 : BIG_CH * 28 + (c - BIG_CH) * 27;
        const int nrows = (c < BIG_CH) ? 28 : 27;

        const float4* xp = reinterpret_cast<const float4*>(x)
                         + (size_t)(b * T_DIM + t0) * COLS4 + tid;

        float4 acc = make_float4(0.f, 0.f, 0.f, 0.f);
#pragma unroll
        for (int t = 0; t < 28; t++) {
            if (t < nrows) {
                float4 v = xp[(size_t)t * COLS4];
                acc.x += v.x; acc.y += v.y; acc.z += v.z; acc.w += v.w;
            }
        }
        // Plain store into this chunk's own slot: zero contention.
        reinterpret_cast<float4*>(&g_part[c][0])[b * COLS4 + tid] = acc;

        __syncthreads();                   // all block stores issued
        if (tid == 0) {
            __threadfence();               // release partials before counter
            atomicAdd((unsigned*)&g_c1, 1u);
        }
    }

    // 264 non-tail blocks exit immediately.
    if (bid >= N_TAIL) return;

    // ---------------- Phase 2: GEMV1 tail (blocks 0..31) -------------------
    __shared__ float s[B_DIM][D_CHUNK];
    const int j  = tid;                    // hidden index (first 256 threads)
    const int d0 = bid * D_CHUNK;

    // Preload this block's W1 chunk into registers BEFORE spinning so the
    // loads overlap with the remaining colsum DRAM traffic.
    float w[D_CHUNK];
    if (j < H_DIM) {
#pragma unroll
        for (int dd = 0; dd < D_CHUNK; dd++)
            w[dd] = W1[(size_t)(d0 + dd) * H_DIM + j];
    }

    if (tid == 0) {
        while (g_c1 < N_BLOCKS) { }        // volatile poll
        __threadfence();                   // acquire
    }
    __syncthreads();

    // Reduce the 74 chunk partials for this block's (b, d) slice into means.
    // 192 slice elements over 384 threads; loads hit L2 (freshly written).
    for (int i = tid; i < B_DIM * D_CHUNK; i += NTHREADS) {
        int b = i / D_CHUNK, dd = i % D_CHUNK;
        int idx = b * E_DIM + d0 + dd;
        float cs = 0.f;
#pragma unroll 2
        for (int p = 0; p < CHUNKS_PB; p++) cs += g_part[p][idx];
        s[b][dd] = cs * (1.0f / (float)T_DIM);
    }
    __syncthreads();

    if (j < H_DIM) {
        float a0 = 0.f, a1 = 0.f, a2 = 0.f, a3 = 0.f;
#pragma unroll
        for (int dd = 0; dd < D_CHUNK; dd++) {
            float ww = w[dd];
            a0 = fmaf(s[0][dd], ww, a0);
            a1 = fmaf(s[1][dd], ww, a1);
            a2 = fmaf(s[2][dd], ww, a2);
            a3 = fmaf(s[3][dd], ww, a3);
        }
        g_hpart[bid][0][j] = a0;
        g_hpart[bid][1][j] = a1;
        g_hpart[bid][2][j] = a2;
        g_hpart[bid][3][j] = a3;
    }

    // ---------------- Phase 3: epilogue in the LAST-arriving tail block ----
    __syncthreads();
    __shared__ unsigned s_last;
    if (tid == 0) {
        __threadfence();                   // release hidden partials
        s_last = (atomicAdd(&g_c2, 1u) == N_TAIL - 1u) ? 1u : 0u;
    }
    __syncthreads();
    if (!s_last) return;

    if (tid == 0) __threadfence();         // acquire all hidden partials
    __syncthreads();

    __shared__ float red[B_DIM][8];
    if (j < H_DIM) {
        const int lane = j & 31, warp = j >> 5;
        float w2 = W2[j];
        float bb = b1[j];
        float v[B_DIM];
#pragma unroll
        for (int b = 0; b < B_DIM; b++) {
            float h = bb;
#pragma unroll
            for (int p = 0; p < N_TAIL; p++) h += g_hpart[p][b][j];
            v[b] = fmaxf(h, 0.0f) * w2;
        }
#pragma unroll
        for (int off = 16; off > 0; off >>= 1)
#pragma unroll
            for (int b = 0; b < B_DIM; b++)
                v[b] += __shfl_down_sync(0xffffffffu, v[b], off);
        if (lane == 0)
#pragma unroll
            for (int b = 0; b < B_DIM; b++) red[b][warp] = v[b];
    }
    __syncthreads();

    if (tid < B_DIM && tid < out_size) {
        float sm = 0.f;
#pragma unroll
        for (int w8 = 0; w8 < 8; w8++) sm += red[tid][w8];
        out[tid] = sm + b2[0];
    }
    // best_action_idx slot: argmax over 32 bit-identical entropies == 0
    // always (int 0 == float 0.0 bit pattern). Zero-fill the rest.
    for (int i = B_DIM + tid; i < out_size; i += NTHREADS)
        out[i] = 0.0f;

    __syncthreads();
    if (tid == 0) { g_c2 = 0u; g_c1 = 0u; __threadfence(); }
}

extern "C" void kernel_launch(void* const* d_in, const int* in_sizes, int n_in,
                              void* d_out, int out_size) {
    const float* x  = (const float*)d_in[0];
    const float* W1 = (const float*)d_in[1];
    const float* b1 = (const float*)d_in[2];
    const float* W2 = (const float*)d_in[3];
    const float* b2 = (const float*)d_in[4];
    float* out = (float*)d_out;

    curiosity_fused<<<N_BLOCKS, NTHREADS>>>(x, W1, b1, W2, b2, out, out_size);
}